// round 2
// baseline (speedup 1.0000x reference)
#include <cuda_runtime.h>
#include <cstdint>
#include <math.h>

#define Bq 128
#define Tq 512
#define Cq 100
#define Eq 64
#define Hq 256
#define G7 1792   // 7*H
#define KIN 320   // E+H

// ---- scratch (device globals; no allocation in kernel_launch) ----
static __device__ float g_r[(size_t)Bq * Tq * Eq];          // 16.8 MB   rec_input
static __device__ float g_gin[(size_t)Bq * Tq * G7];        // 470 MB    input-side gates (+bias)
static __device__ __align__(16) float g_h[2][16][Hq][8];    // ping-pong h_d, [buf][group][j][b]

__device__ __forceinline__ float sigmf_(float x) { return 1.f / (1.f + expf(-x)); }
__device__ __forceinline__ float softplusf_(float x) {
    return fmaxf(x, 0.f) + log1pf(expf(-fabsf(x)));
}

// ---------------------------------------------------------------------------
// K1: rec_input[b,t,e] = (marks[b,t,:] @ W_emb[:,e]) / max(sum(marks),1)
// ---------------------------------------------------------------------------
__global__ __launch_bounds__(128) void k_embed(const float* __restrict__ marks,
                                               const float* __restrict__ Wemb) {
    int bt = blockIdx.x;
    __shared__ float sm[Cq];
    int tid = threadIdx.x;
    if (tid < Cq) sm[tid] = marks[(size_t)bt * Cq + tid];
    __syncthreads();
    if (tid < Eq) {
        float cnt = 0.f, s = 0.f;
        #pragma unroll
        for (int c = 0; c < Cq; c++) {
            float m = sm[c];
            cnt += m;
            s = fmaf(m, Wemb[c * Eq + tid], s);
        }
        g_r[(size_t)bt * Eq + tid] = s / fmaxf(cnt, 1.f);
    }
}

// ---------------------------------------------------------------------------
// K2: g_gin[bt, j] = g_r[bt,:] @ W_cell[j, 0:64]^T + b_cell[j]
// ---------------------------------------------------------------------------
__global__ __launch_bounds__(256) void k_gin(const float* __restrict__ Wc,
                                             const float* __restrict__ bc) {
    __shared__ float As[64 * 68];    // As[k*68 + row]
    __shared__ float Bs[64 * 132];   // Bs[k*132 + col]
    int tid = threadIdx.x;
    int row0 = blockIdx.x * 64, col0 = blockIdx.y * 128;

    #pragma unroll
    for (int i = 0; i < 16; i++) {
        int idx = i * 256 + tid;
        int row = idx >> 6, k = idx & 63;
        As[k * 68 + row] = g_r[(size_t)(row0 + row) * Eq + k];
    }
    #pragma unroll
    for (int i = 0; i < 32; i++) {
        int idx = i * 256 + tid;
        int col = idx >> 6, k = idx & 63;
        Bs[k * 132 + col] = Wc[(size_t)(col0 + col) * KIN + k];
    }
    __syncthreads();

    int tx = tid & 15, ty = tid >> 4;
    float acc[4][8];
    #pragma unroll
    for (int i = 0; i < 4; i++)
        #pragma unroll
        for (int jx = 0; jx < 8; jx++) acc[i][jx] = 0.f;

    #pragma unroll 4
    for (int k = 0; k < 64; k++) {
        float4 a  = *(const float4*)&As[k * 68 + ty * 4];
        float4 b0 = *(const float4*)&Bs[k * 132 + tx * 8];
        float4 b1 = *(const float4*)&Bs[k * 132 + tx * 8 + 4];
        float av[4] = {a.x, a.y, a.z, a.w};
        float bv[8] = {b0.x, b0.y, b0.z, b0.w, b1.x, b1.y, b1.z, b1.w};
        #pragma unroll
        for (int i = 0; i < 4; i++)
            #pragma unroll
            for (int jx = 0; jx < 8; jx++)
                acc[i][jx] = fmaf(av[i], bv[jx], acc[i][jx]);
    }

    float bb[8];
    #pragma unroll
    for (int jx = 0; jx < 8; jx++) bb[jx] = bc[col0 + tx * 8 + jx];

    #pragma unroll
    for (int i = 0; i < 4; i++) {
        size_t base = (size_t)(row0 + ty * 4 + i) * G7 + col0 + tx * 8;
        float4 o0 = {acc[i][0] + bb[0], acc[i][1] + bb[1], acc[i][2] + bb[2], acc[i][3] + bb[3]};
        float4 o1 = {acc[i][4] + bb[4], acc[i][5] + bb[5], acc[i][6] + bb[6], acc[i][7] + bb[7]};
        *(float4*)&g_gin[base]     = o0;
        *(float4*)&g_gin[base + 4] = o1;
    }
}

// ---------------------------------------------------------------------------
// K3: initial state -> out[b,0,:] and g_h[0]  (g_h layout [buf][group][j][b])
// ---------------------------------------------------------------------------
__global__ __launch_bounds__(256) void k_init(const float* __restrict__ init,
                                              float* __restrict__ out) {
    int b = blockIdx.x, k = threadIdx.x;
    float s0 = init[k], s1 = init[Hq + k], s2 = init[2 * Hq + k];
    float s3 = init[3 * Hq + k], s4 = init[4 * Hq + k], s5 = init[5 * Hq + k];
    float hd0 = tanhf(s0), cd0 = tanhf(s1), cb0 = tanhf(s2), c0 = tanhf(s3);
    float d0 = softplusf_(s4), o0 = sigmf_(s5);
    size_t base = (size_t)b * (Tq + 1) * (6 * Hq);
    out[base + 0 * Hq + k] = hd0;
    out[base + 1 * Hq + k] = o0;
    out[base + 2 * Hq + k] = cb0;
    out[base + 3 * Hq + k] = c0;
    out[base + 4 * Hq + k] = d0;
    out[base + 5 * Hq + k] = cd0;
    g_h[0][b >> 3][k][b & 7] = hd0;
}

// ---------------------------------------------------------------------------
// K4: sequential recurrence. Cluster of 8 CTAs per batch-group of 8.
//   rank r owns j in [32r, 32r+32) across all 7 gates.
//   128 threads: jj = tid&31, batch-pair b0 = 2*(tid>>5). Thread tile = 2b x 7g.
//   Weights SoA by gate in SMEM, xor-swizzled: Ws[((g*256+k)<<5) + (jj^(k&31))].
//   h exchanged through L2 (stcg/ldcg broadcast) + 1 cluster barrier / step.
//   No __syncthreads inside the step loop.
// ---------------------------------------------------------------------------
__global__ void __cluster_dims__(8, 1, 1) __launch_bounds__(128, 1)
k_recur(const float* __restrict__ Wc, const float* __restrict__ ts,
        const float* __restrict__ init, float* __restrict__ out) {
    extern __shared__ float Ws[];   // 7*256*32 floats = 229,376 B

    int tid = threadIdx.x;
    int jj = tid & 31;
    int bt = tid >> 5;              // 0..3
    int b0 = bt * 2;                // local batch pair
    int rank = blockIdx.x & 7, group = blockIdx.x >> 3;
    int j = rank * 32 + jj;
    int bg = group * 8 + b0;        // global batch index of lane's first batch

    // one-time weight load: LDG coalesced along k, STS conflict-free via swizzle
    for (int idx = tid; idx < 7 * 256 * 32; idx += 128) {
        int k = idx & 255;
        int r = idx >> 8;           // g*32 + jjw
        int jjw = r & 31, g = r >> 5;
        int row = g * Hq + rank * 32 + jjw;
        Ws[((g * 256 + k) << 5) + (jjw ^ (k & 31))] = Wc[(size_t)row * KIN + Eq + k];
    }

    float cinit  = tanhf(init[3 * Hq + j]);
    float cbinit = tanhf(init[2 * Hq + j]);
    float c_st[2]  = {cinit, cinit};
    float cb_st[2] = {cbinit, cbinit};
    __syncthreads();

    for (int t = 0; t < Tq; t++) {
        const float* hsrc = &g_h[t & 1][group][0][0];
        float* hdst       = &g_h[(t & 1) ^ 1][group][0][0];

        // prefetch input-side gates (+bias) and timestamps (independent of h)
        float a[2][7];
        float tc[2], tp[2];
        #pragma unroll
        for (int i = 0; i < 2; i++) {
            size_t gbase = ((size_t)(bg + i) * Tq + t) * (size_t)G7 + j;
            #pragma unroll
            for (int g = 0; g < 7; g++) a[i][g] = __ldcs(&g_gin[gbase + g * Hq]);
            tc[i] = ts[(bg + i) * Tq + t];
            tp[i] = (t > 0) ? ts[(bg + i) * Tq + t - 1] : 0.f;
        }

        float acc[2][7];
        #pragma unroll
        for (int i = 0; i < 2; i++)
            #pragma unroll
            for (int g = 0; g < 7; g++) acc[i][g] = 0.f;

        #pragma unroll 1
        for (int kb = 0; kb < 256; kb += 8) {
            float2 hb[8];
            #pragma unroll
            for (int i = 0; i < 8; i++)
                hb[i] = __ldcg((const float2*)(hsrc + (size_t)(kb + i) * 8 + b0));
            #pragma unroll
            for (int i = 0; i < 8; i++) {
                int k = kb + i;
                const float* w = Ws + (k << 5) + (jj ^ (k & 31));
                #pragma unroll
                for (int g = 0; g < 7; g++) {
                    float wv = w[g * 8192];
                    acc[0][g] = fmaf(wv, hb[i].x, acc[0][g]);
                    acc[1][g] = fmaf(wv, hb[i].y, acc[1][g]);
                }
            }
        }

        #pragma unroll
        for (int i = 0; i < 2; i++) {
            float gi  = sigmf_(a[i][0] + acc[i][0]);
            float gf  = sigmf_(a[i][1] + acc[i][1]);
            float gz  = tanhf(a[i][2] + acc[i][2]);
            float go  = sigmf_(a[i][3] + acc[i][3]);
            float gib = sigmf_(a[i][4] + acc[i][4]);
            float gfb = sigmf_(a[i][5] + acc[i][5]);
            float gd  = softplusf_(a[i][6] + acc[i][6]);
            float dt  = tc[i] - tp[i];

            float ct  = gf * c_st[i] + gi * gz;
            float cbt = gfb * cb_st[i] + gib * gz;
            float cdt = cbt + (ct - cbt) * expf(-gd * dt);
            float hdt = go * tanhf(cdt);

            size_t ob = ((size_t)(bg + i) * (Tq + 1) + t + 1) * (size_t)(6 * Hq) + j;
            out[ob + 0 * Hq] = hdt;
            out[ob + 1 * Hq] = go;
            out[ob + 2 * Hq] = cbt;
            out[ob + 3 * Hq] = ct;
            out[ob + 4 * Hq] = gd;
            out[ob + 5 * Hq] = cdt;

            c_st[i] = ct; cb_st[i] = cbt;
            __stcg(&hdst[(size_t)j * 8 + b0 + i], hdt);
        }

        // cluster barrier: release h writes / acquire peers' h for next step
        asm volatile("barrier.cluster.arrive.aligned;" ::: "memory");
        asm volatile("barrier.cluster.wait.aligned;" ::: "memory");
    }
}

// ---------------------------------------------------------------------------
extern "C" void kernel_launch(void* const* d_in, const int* in_sizes, int n_in,
                              void* d_out, int out_size) {
    const float* marks = (const float*)d_in[0];
    const float* ts    = (const float*)d_in[1];
    const float* Wemb  = (const float*)d_in[2];
    const float* Wc    = (const float*)d_in[3];
    const float* bc    = (const float*)d_in[4];
    const float* init  = (const float*)d_in[5];
    float* out = (float*)d_out;

    k_embed<<<Bq * Tq, 128>>>(marks, Wemb);
    k_gin<<<dim3((Bq * Tq) / 64, G7 / 128), 256>>>(Wc, bc);
    k_init<<<Bq, 256>>>(init, out);

    const int SMEM = 7 * 256 * 32 * (int)sizeof(float);   // 229,376 B
    cudaFuncSetAttribute(k_recur, cudaFuncAttributeMaxDynamicSharedMemorySize, SMEM);
    k_recur<<<128, 128, SMEM>>>(Wc, ts, init, out);
}

// round 3
// speedup vs baseline: 4.1206x; 4.1206x over previous
#include <cuda_runtime.h>
#include <cstdint>
#include <math.h>

#define Bq 128
#define Tq 512
#define Cq 100
#define Eq 64
#define Hq 256
#define G7 1792   // 7*H
#define KIN 320   // E+H

typedef unsigned long long ull;

// ---- scratch (device globals; no allocation in kernel_launch) ----
static __device__ float g_r[(size_t)Bq * Tq * Eq];          // rec_input
static __device__ float g_gin[(size_t)Bq * Tq * G7];        // input-side gates (+bias)
static __device__ __align__(16) float g_h[2][Bq][Hq];       // ping-pong h_d [buf][b][j]
static __device__ unsigned g_cnt[8];                        // per-group step counters

__device__ __forceinline__ float sigmf_(float x) { return 1.f / (1.f + expf(-x)); }
__device__ __forceinline__ float softplusf_(float x) {
    return fmaxf(x, 0.f) + log1pf(expf(-fabsf(x)));
}
__device__ __forceinline__ void fma2_(ull& d, ull a, ull b) {
    asm volatile("fma.rn.f32x2 %0, %1, %2, %0;" : "+l"(d) : "l"(a), "l"(b));
}
__device__ __forceinline__ float lo_(ull v) { return __uint_as_float((unsigned)v); }
__device__ __forceinline__ float hi_(ull v) { return __uint_as_float((unsigned)(v >> 32)); }

// ---------------------------------------------------------------------------
// K1: rec_input
// ---------------------------------------------------------------------------
__global__ __launch_bounds__(128) void k_embed(const float* __restrict__ marks,
                                               const float* __restrict__ Wemb) {
    int bt = blockIdx.x;
    __shared__ float sm[Cq];
    int tid = threadIdx.x;
    if (tid < Cq) sm[tid] = marks[(size_t)bt * Cq + tid];
    __syncthreads();
    if (tid < Eq) {
        float cnt = 0.f, s = 0.f;
        #pragma unroll
        for (int c = 0; c < Cq; c++) {
            float m = sm[c];
            cnt += m;
            s = fmaf(m, Wemb[c * Eq + tid], s);
        }
        g_r[(size_t)bt * Eq + tid] = s / fmaxf(cnt, 1.f);
    }
}

// ---------------------------------------------------------------------------
// K2: g_gin[bt, j] = g_r[bt,:] @ W_cell[j, 0:64]^T + b_cell[j]
// ---------------------------------------------------------------------------
__global__ __launch_bounds__(256) void k_gin(const float* __restrict__ Wc,
                                             const float* __restrict__ bc) {
    __shared__ float As[64 * 68];
    __shared__ float Bs[64 * 132];
    int tid = threadIdx.x;
    int row0 = blockIdx.x * 64, col0 = blockIdx.y * 128;

    #pragma unroll
    for (int i = 0; i < 16; i++) {
        int idx = i * 256 + tid;
        int row = idx >> 6, k = idx & 63;
        As[k * 68 + row] = g_r[(size_t)(row0 + row) * Eq + k];
    }
    #pragma unroll
    for (int i = 0; i < 32; i++) {
        int idx = i * 256 + tid;
        int col = idx >> 6, k = idx & 63;
        Bs[k * 132 + col] = Wc[(size_t)(col0 + col) * KIN + k];
    }
    __syncthreads();

    int tx = tid & 15, ty = tid >> 4;
    float acc[4][8];
    #pragma unroll
    for (int i = 0; i < 4; i++)
        #pragma unroll
        for (int jx = 0; jx < 8; jx++) acc[i][jx] = 0.f;

    #pragma unroll 4
    for (int k = 0; k < 64; k++) {
        float4 a  = *(const float4*)&As[k * 68 + ty * 4];
        float4 b0 = *(const float4*)&Bs[k * 132 + tx * 8];
        float4 b1 = *(const float4*)&Bs[k * 132 + tx * 8 + 4];
        float av[4] = {a.x, a.y, a.z, a.w};
        float bv[8] = {b0.x, b0.y, b0.z, b0.w, b1.x, b1.y, b1.z, b1.w};
        #pragma unroll
        for (int i = 0; i < 4; i++)
            #pragma unroll
            for (int jx = 0; jx < 8; jx++)
                acc[i][jx] = fmaf(av[i], bv[jx], acc[i][jx]);
    }

    float bb[8];
    #pragma unroll
    for (int jx = 0; jx < 8; jx++) bb[jx] = bc[col0 + tx * 8 + jx];

    #pragma unroll
    for (int i = 0; i < 4; i++) {
        size_t base = (size_t)(row0 + ty * 4 + i) * G7 + col0 + tx * 8;
        float4 o0 = {acc[i][0] + bb[0], acc[i][1] + bb[1], acc[i][2] + bb[2], acc[i][3] + bb[3]};
        float4 o1 = {acc[i][4] + bb[4], acc[i][5] + bb[5], acc[i][6] + bb[6], acc[i][7] + bb[7]};
        *(float4*)&g_gin[base]     = o0;
        *(float4*)&g_gin[base + 4] = o1;
    }
}

// ---------------------------------------------------------------------------
// K3: initial state -> out[b,0,:], g_h[0], reset sync counters
// ---------------------------------------------------------------------------
__global__ __launch_bounds__(256) void k_init(const float* __restrict__ init,
                                              float* __restrict__ out) {
    int b = blockIdx.x, k = threadIdx.x;
    if (b == 0 && k < 8) g_cnt[k] = 0;
    float s0 = init[k], s1 = init[Hq + k], s2 = init[2 * Hq + k];
    float s3 = init[3 * Hq + k], s4 = init[4 * Hq + k], s5 = init[5 * Hq + k];
    float hd0 = tanhf(s0), cd0 = tanhf(s1), cb0 = tanhf(s2), c0 = tanhf(s3);
    float d0 = softplusf_(s4), o0 = sigmf_(s5);
    size_t base = (size_t)b * (Tq + 1) * (6 * Hq);
    out[base + 0 * Hq + k] = hd0;
    out[base + 1 * Hq + k] = o0;
    out[base + 2 * Hq + k] = cb0;
    out[base + 3 * Hq + k] = c0;
    out[base + 4 * Hq + k] = d0;
    out[base + 5 * Hq + k] = cd0;
    g_h[0][b][k] = hd0;
}

// ---------------------------------------------------------------------------
// K4: recurrence. grid = 128 = 8 batch-groups (16 b) x 16 j-slices (16 j).
//   256 threads. Phase 1 (GEMM): warp = (kw 0..3, bqp 0..1); lane = (j1 0..15,
//   bql 0..1); thread tile = 7 gates x 4 batches, k-range 64, fma.rn.f32x2
//   packed along k. Phase 2: thread = (j2, b2) reduces 4 k-partials for all
//   7 gates, applies nonlinearities/decay, writes outputs + h.
//   h exchanged via L2; per-group software release/acquire barrier per step.
// ---------------------------------------------------------------------------
__global__ void __launch_bounds__(256, 1)
k_recur(const float* __restrict__ Wc, const float* __restrict__ ts,
        const float* __restrict__ init, float* __restrict__ out) {
    extern __shared__ float sh[];
    float* Ws  = sh;            // 7*64*16*4 = 28672 floats: [(g*64+k4)*16+j][4]
    float* hs  = sh + 28672;    // 4096 floats: [b][k] (b local 0..15)
    float* red = sh + 32768;    // 7168 floats: [((kw*7+g)*4+bq)*16+j][4b]

    int tid = threadIdx.x;
    int group = blockIdx.x >> 4;     // 0..7
    int rank  = blockIdx.x & 15;     // 0..15
    int j0 = rank * 16;

    // phase-1 identity
    int w = tid >> 5, lane = tid & 31;
    int kw = w & 3, bqp = w >> 2;
    int j1 = lane & 15, bql = lane >> 4;
    int bq = bqp * 2 + bql, b0 = bq * 4;

    // phase-2 identity
    int j2 = tid & 15, b2 = tid >> 4;
    int jg2 = j0 + j2;
    int bg2 = group * 16 + b2;
    int bq2 = b2 >> 2, bl2 = b2 & 3;

    // one-time weight load: LDG coalesced along k
    {
        int k = tid;
        for (int gj = 0; gj < 112; gj++) {
            int g = gj >> 4, jw = gj & 15;
            int row = g * Hq + j0 + jw;
            Ws[((g * 64 + (k >> 2)) * 16 + jw) * 4 + (k & 3)] =
                Wc[(size_t)row * KIN + Eq + k];
        }
    }

    float c_st  = tanhf(init[3 * Hq + jg2]);
    float cb_st = tanhf(init[2 * Hq + jg2]);
    __syncthreads();

    const float* wsj = Ws + j1 * 4;
    float4* hs4 = (float4*)hs;
    float4* red4 = (float4*)red;

    for (int t = 0; t < Tq; t++) {
        // ---- stage h (16 b x 256 k) from L2 ----
        const float4* gsrc = (const float4*)&g_h[t & 1][group * 16][0];
        #pragma unroll
        for (int r = 0; r < 4; r++)
            hs4[tid + 256 * r] = __ldcg(gsrc + tid + 256 * r);

        // ---- prefetch input-side gates + timestamps (phase-2 identity) ----
        float ain[7];
        size_t gbase = ((size_t)bg2 * Tq + t) * (size_t)G7 + jg2;
        #pragma unroll
        for (int g = 0; g < 7; g++) ain[g] = __ldcs(&g_gin[gbase + g * Hq]);
        float tc = ts[bg2 * Tq + t];
        float tp = (t > 0) ? ts[bg2 * Tq + t - 1] : 0.f;
        __syncthreads();

        // ---- phase 1: packed-f32x2 GEMM, k-range [kw*64, kw*64+64) ----
        ull acc2[7][4];
        #pragma unroll
        for (int g = 0; g < 7; g++)
            #pragma unroll
            for (int r = 0; r < 4; r++) acc2[g][r] = 0ull;

        int kbase = kw * 64;
        #pragma unroll 4
        for (int q = 0; q < 16; q++) {
            int k = kbase + q * 4;
            ulonglong2 hv[4];
            #pragma unroll
            for (int r = 0; r < 4; r++)
                hv[r] = *(const ulonglong2*)&hs[(b0 + r) * 256 + k];
            #pragma unroll
            for (int g = 0; g < 7; g++) {
                ulonglong2 wv = *(const ulonglong2*)&wsj[((g * 64 + kw * 16 + q) << 6)];
                #pragma unroll
                for (int r = 0; r < 4; r++) {
                    fma2_(acc2[g][r], wv.x, hv[r].x);
                    fma2_(acc2[g][r], wv.y, hv[r].y);
                }
            }
        }

        // ---- store k-partials ----
        #pragma unroll
        for (int g = 0; g < 7; g++) {
            float4 v;
            v.x = lo_(acc2[g][0]) + hi_(acc2[g][0]);
            v.y = lo_(acc2[g][1]) + hi_(acc2[g][1]);
            v.z = lo_(acc2[g][2]) + hi_(acc2[g][2]);
            v.w = lo_(acc2[g][3]) + hi_(acc2[g][3]);
            red4[((kw * 7 + g) * 4 + bq) * 16 + j1] = v;
        }
        __syncthreads();

        // ---- phase 2: reduce + nonlinearities + decay + writes ----
        float gate[7];
        #pragma unroll
        for (int g = 0; g < 7; g++) {
            int idx = ((g * 4 + bq2) * 16 + j2) * 4 + bl2;
            float s = red[idx]
                    + red[idx + 7 * 4 * 16 * 4]
                    + red[idx + 14 * 4 * 16 * 4]
                    + red[idx + 21 * 4 * 16 * 4];
            gate[g] = s + ain[g];
        }

        float gi  = sigmf_(gate[0]);
        float gf  = sigmf_(gate[1]);
        float gz  = tanhf(gate[2]);
        float go  = sigmf_(gate[3]);
        float gib = sigmf_(gate[4]);
        float gfb = sigmf_(gate[5]);
        float gd  = softplusf_(gate[6]);
        float dt  = tc - tp;

        float ct  = gf * c_st + gi * gz;
        float cbt = gfb * cb_st + gib * gz;
        float cdt = cbt + (ct - cbt) * expf(-gd * dt);
        float hdt = go * tanhf(cdt);

        size_t ob = ((size_t)bg2 * (Tq + 1) + t + 1) * (size_t)(6 * Hq) + jg2;
        __stcs(&out[ob + 0 * Hq], hdt);
        __stcs(&out[ob + 1 * Hq], go);
        __stcs(&out[ob + 2 * Hq], cbt);
        __stcs(&out[ob + 3 * Hq], ct);
        __stcs(&out[ob + 4 * Hq], gd);
        __stcs(&out[ob + 5 * Hq], cdt);

        c_st = ct; cb_st = cbt;
        __stcg(&g_h[(t & 1) ^ 1][bg2][jg2], hdt);

        // ---- per-group software barrier (release/acquire through L2) ----
        __threadfence();
        __syncthreads();
        if (tid == 0) {
            atomicAdd(&g_cnt[group], 1u);
            unsigned target = 16u * (unsigned)(t + 1), v;
            do {
                asm volatile("ld.acquire.gpu.u32 %0, [%1];"
                             : "=r"(v) : "l"(&g_cnt[group]) : "memory");
            } while (v < target);
        }
        __syncthreads();
    }
}

// ---------------------------------------------------------------------------
extern "C" void kernel_launch(void* const* d_in, const int* in_sizes, int n_in,
                              void* d_out, int out_size) {
    const float* marks = (const float*)d_in[0];
    const float* ts    = (const float*)d_in[1];
    const float* Wemb  = (const float*)d_in[2];
    const float* Wc    = (const float*)d_in[3];
    const float* bc    = (const float*)d_in[4];
    const float* init  = (const float*)d_in[5];
    float* out = (float*)d_out;

    k_embed<<<Bq * Tq, 128>>>(marks, Wemb);
    k_gin<<<dim3((Bq * Tq) / 64, G7 / 128), 256>>>(Wc, bc);
    k_init<<<Bq, 256>>>(init, out);

    const int SMEM = (28672 + 4096 + 7168) * (int)sizeof(float);   // 159,744 B
    cudaFuncSetAttribute(k_recur, cudaFuncAttributeMaxDynamicSharedMemorySize, SMEM);
    k_recur<<<128, 256, SMEM>>>(Wc, ts, init, out);
}